// round 12
// baseline (speedup 1.0000x reference)
#include <cuda_runtime.h>
#include <cuda_fp16.h>
#include <cstdint>

#define BATCH 16
#define CCH   512
#define CIN   256
#define NUM   1024

// ---------------------------------------------------------------------------
// Fragment-major global buffers (u32 = fp16 k-pair), hi-precision only.
// A-layout: [k16][m16][128]  lane l owns u32 l*4+{0..3} = {a0,a1,a2,a3}
// B-layout: [k16][n8][64]    lane l owns u32 l*2+{0,1}  = {b0,b1}
// ---------------------------------------------------------------------------
__device__ uint32_t u_XA0[4194304];  // bn1(rgb)  A-layout [16][32][64][128]
__device__ uint32_t u_XA1[4194304];  // bn1(flow)
__device__ uint32_t u_XA2[4194304];  // bn2(flow)
__device__ uint32_t u_XA3[4194304];  // bn2(rgb)
__device__ uint32_t u_XB0[4194304];  // bn1(rgb)  B-layout
__device__ uint32_t u_XB1[4194304];  // bn2(flow) B-layout
__device__ uint32_t u_TH[4194304];   // theta A-layout [32][16][64][128]
__device__ uint32_t u_PH[4194304];   // phi   B-layout [32][16][128][64]
__device__ uint32_t u_G [4194304];   // g     B-layout [32][64][32][64]
__device__ uint32_t u_Y [4194304];   // y     B-layout [32][16][128][64]
__device__ uint32_t u_W [524288];    // 8 mats: th/ph B-layout, g/w A-layout
__device__ uint32_t u_P [16777216];  // probs row-major [32][1024][512 u32]
__device__ float    g_S [33554432];  // logits fp32 [32][1024][1024]
__device__ int      g_cnt[256];      // per (z, row-block) completion counters

__device__ __forceinline__ uint32_t* xbufA(int s) {
    switch (s) { case 0: return u_XA0; case 1: return u_XA1;
                 case 2: return u_XA2; default: return u_XA3; }
}

// ---------------------------------------------------------------------------
// Helpers
// ---------------------------------------------------------------------------
__device__ __forceinline__ uint32_t smem_u32(const void* p) {
    uint32_t a;
    asm("{ .reg .u64 t; cvta.to.shared.u64 t, %1; cvt.u32.u64 %0, t; }" : "=r"(a) : "l"(p));
    return a;
}
__device__ __forceinline__ void cp16(uint32_t dst, const void* src) {
    asm volatile("cp.async.cg.shared.global [%0], [%1], 16;" :: "r"(dst), "l"(src));
}
#define CP_COMMIT() asm volatile("cp.async.commit_group;")
template <int N>
__device__ __forceinline__ void cp_wait() {
    asm volatile("cp.async.wait_group %0;" :: "n"(N));
}

__device__ __forceinline__ uint32_t packh1(float x, float y) {
    __half2 H = __halves2half2(__float2half_rn(x), __float2half_rn(y));
    return *reinterpret_cast<uint32_t*>(&H);
}

__device__ __forceinline__ void mma16816(float c[4], const uint32_t a[4],
                                         uint32_t b0, uint32_t b1) {
    asm volatile(
        "mma.sync.aligned.m16n8k16.row.col.f32.f16.f16.f32 "
        "{%0,%1,%2,%3}, {%4,%5,%6,%7}, {%8,%9}, {%0,%1,%2,%3};"
        : "+f"(c[0]), "+f"(c[1]), "+f"(c[2]), "+f"(c[3])
        : "r"(a[0]), "r"(a[1]), "r"(a[2]), "r"(a[3]), "r"(b0), "r"(b1));
}

// ---------------------------------------------------------------------------
// Fused prep: BN+ReLU fragment tiles (blocks 0..4095) + weight prep (4096..4607).
// ---------------------------------------------------------------------------
__global__ void prep_all(const float* __restrict__ rgb, const float* __restrict__ flow,
                         const float* __restrict__ g1, const float* __restrict__ b1,
                         const float* __restrict__ m1, const float* __restrict__ v1,
                         const float* __restrict__ g2, const float* __restrict__ b2,
                         const float* __restrict__ m2, const float* __restrict__ v2,
                         const float* w0, const float* w1, const float* w2, const float* w3,
                         const float* w4, const float* w5, const float* w6, const float* w7)
{
    const int bid = blockIdx.x;
    const int warp = threadIdx.x >> 5, lane = threadIdx.x & 31;
    const int grp = lane >> 2, tig = lane & 3;

    if (bid < 4096) {
        // ---- BN+ReLU part ----
        const int z = bid >> 8;
        const int id = (bid & 255) * 8 + warp;
        const int t_k = id & 31, t_n = id >> 5;
        const int n0 = t_n * 16;

        int c[4];
        c[0] = t_k * 16 + 2 * tig; c[1] = c[0] + 1; c[2] = c[0] + 8; c[3] = c[2] + 1;

        float s1[4], h1[4], s2[4], h2[4];
#pragma unroll
        for (int e = 0; e < 4; e++) {
            s1[e] = g1[c[e]] * rsqrtf(v1[c[e]] + 1e-5f);
            h1[e] = b1[c[e]] - m1[c[e]] * s1[e];
            s2[e] = g2[c[e]] * rsqrtf(v2[c[e]] + 1e-5f);
            h2[e] = b2[c[e]] - m2[c[e]] * s2[e];
        }

        float R[2][4], Fv[2][4];
#pragma unroll
        for (int h = 0; h < 2; h++)
#pragma unroll
            for (int e = 0; e < 4; e++) {
                const long long idx = (long long)(z * CCH + c[e]) * NUM + n0 + grp + h * 8;
                R[h][e] = rgb[idx];
                Fv[h][e] = flow[idx];
            }

        auto bnr = [](float x, float s, float h) { return fmaxf(fmaf(x, s, h), 0.f); };
        const long long aoff = (long long)z * 262144 + (t_k * 64 + t_n) * 128 + lane * 4;
        const long long boff = (long long)z * 262144 + (long long)(t_k * 128 + t_n * 2) * 64 + lane * 2;

        float V[2][4];
        auto doStream = [&](const float (*X)[4], const float* sc, const float* sh,
                            uint32_t* bufA, uint32_t* bufB) {
#pragma unroll
            for (int h = 0; h < 2; h++)
#pragma unroll
                for (int e = 0; e < 4; e++) V[h][e] = bnr(X[h][e], sc[e], sh[e]);
            const uint32_t H0 = packh1(V[0][0], V[0][1]);
            const uint32_t H1 = packh1(V[1][0], V[1][1]);
            const uint32_t H2 = packh1(V[0][2], V[0][3]);
            const uint32_t H3 = packh1(V[1][2], V[1][3]);
            *reinterpret_cast<uint4*>(bufA + aoff) = make_uint4(H0, H1, H2, H3);
            if (bufB) {
                *reinterpret_cast<uint2*>(bufB + boff)      = make_uint2(H0, H2);
                *reinterpret_cast<uint2*>(bufB + boff + 64) = make_uint2(H1, H3);
            }
        };
        doStream(R,  s1, h1, u_XA0, u_XB0);
        doStream(Fv, s1, h1, u_XA1, nullptr);
        doStream(Fv, s2, h2, u_XA2, u_XB1);
        doStream(R,  s2, h2, u_XA3, nullptr);
    } else {
        // ---- weight prep part ----
        const int w = bid - 4096;
        const int mat = w >> 6;
        const bool isW = ((mat & 3) == 3);
        const int din  = isW ? 256 : 512;
        const int dout = isW ? 512 : 256;
        const bool Asw = ((mat & 3) >= 2);
        const int id = (w & 63) * 8 + warp;
        const int kT = din >> 4;
        const int t_k = id % kT, t_m = id / kT;

        const float* src;
        switch (mat) {
            case 0: src = w0; break; case 1: src = w1; break;
            case 2: src = w2; break; case 3: src = w3; break;
            case 4: src = w4; break; case 5: src = w5; break;
            case 6: src = w6; break; default: src = w7; break;
        }

        uint32_t u[2][2];
#pragma unroll
        for (int h = 0; h < 2; h++)
#pragma unroll
            for (int q = 0; q < 2; q++) {
                const int row = t_m * 16 + grp + h * 8;
                const int col = t_k * 16 + 2 * tig + 8 * q;
                const float2 f = *reinterpret_cast<const float2*>(src + (long long)row * din + col);
                u[h][q] = packh1(f.x, f.y);
            }
        uint32_t* base = u_W + mat * 65536;
        if (Asw) {
            *reinterpret_cast<uint4*>(base + (t_k * (dout >> 4) + t_m) * 128 + lane * 4) =
                make_uint4(u[0][0], u[1][0], u[0][1], u[1][1]);
        } else {
#pragma unroll
            for (int h = 0; h < 2; h++)
                *reinterpret_cast<uint2*>(base + (t_k * (dout >> 3) + t_m * 2 + h) * 64 + lane * 2) =
                    make_uint2(u[h][0], u[h][1]);
        }
    }
}

// ---------------------------------------------------------------------------
// Merged theta/phi/g GEMM. grid (16, 1, 96): zz<64 -> thph, zz>=64 -> g.
// 1-term fp16, fragment-major operands, 6-stage k32 cp.async pipeline.
// ---------------------------------------------------------------------------
__global__ __launch_bounds__(256, 2)
void gemm01(const float* __restrict__ tb1, const float* __restrict__ pb1,
            const float* __restrict__ tb2, const float* __restrict__ pb2,
            const float* __restrict__ gb1, const float* __restrict__ gb2)
{
    constexpr int BBu = 2048, STGU = 4096, NSTG = 6, S = 16;  // K = 512

    extern __shared__ uint32_t sm[];
    const uint32_t smb = smem_u32(sm);
    const int tid  = threadIdx.x;
    const int lane = tid & 31;
    const int warp = tid >> 5;
    const int grp  = lane >> 2;
    const int tig  = lane & 3;
    const int wm   = warp & 3;
    const int wn   = warp >> 2;
    const int tx   = blockIdx.x;
    const int zz   = blockIdx.z;

    const uint32_t *Ah, *Bh;
    const float* bias;
    uint32_t* OU;
    int MTr, NT8r, m0, n0, mat;

    if (zz < 64) {
        const int batch = zz & 15, sel = zz >> 4, blk = sel >> 1;
        mat = sel & 1;
        Ah = xbufA(sel) + (long long)batch * 262144;
        Bh = u_W + (blk * 4 + mat) * 65536;
        bias = (sel == 0) ? tb1 : (sel == 1) ? pb1 : (sel == 2) ? tb2 : pb2;
        OU = (mat ? u_PH : u_TH) + (long long)(blk * 16 + batch) * 131072;
        MTr = 64; NT8r = 32;
        m0 = (tx >> 1) * 128; n0 = (tx & 1) * 128;
    } else {
        const int z2 = zz - 64, blk = z2 >> 4, batch = z2 & 15;
        mat = 2;
        Ah = u_W + (blk * 4 + 2) * 65536;
        Bh = (blk ? u_XB1 : u_XB0) + (long long)batch * 262144;
        bias = blk ? gb2 : gb1;
        OU = u_G + (long long)z2 * 131072;
        MTr = 16; NT8r = 128;
        m0 = (tx & 1) * 128; n0 = (tx >> 1) * 128;
    }

    const int m0t = m0 >> 4, n0t = n0 >> 3;

    auto issueAB = [&](int s, int buf) {
        const uint32_t base = smb + buf * STGU * 4;
#pragma unroll
        for (int i = 0; i < 2; i++) {
            const int c = tid + i * 256;
            const int kk = c >> 8, inner = c & 255;
            cp16(base + (c * 4) * 4,
                 Ah + (long long)((s * 2 + kk) * MTr + m0t) * 128 + inner * 4);
        }
#pragma unroll
        for (int i = 0; i < 2; i++) {
            const int c = tid + i * 256;
            const int kk = c >> 8, inner = c & 255;
            cp16(base + ((BBu + c * 4)) * 4,
                 Bh + (long long)((s * 2 + kk) * NT8r + n0t) * 64 + inner * 4);
        }
    };

    float acc[2][8][4];
#pragma unroll
    for (int i = 0; i < 2; i++)
#pragma unroll
        for (int j = 0; j < 8; j++)
#pragma unroll
            for (int q = 0; q < 4; q++) acc[i][j][q] = 0.f;

#pragma unroll
    for (int i = 0; i < NSTG - 1; i++) { issueAB(i, i); CP_COMMIT(); }
    cp_wait<NSTG - 2>();
    __syncthreads();

    int bufC = 0, bufI = NSTG - 1;
    for (int s = 0; s < S; s++) {
        if (s + NSTG - 1 < S) { issueAB(s + NSTG - 1, bufI); CP_COMMIT(); }
        {
            const uint32_t* st = sm + bufC * STGU;
#pragma unroll
            for (int kk = 0; kk < 2; kk++) {
                uint32_t ah[2][4];
#pragma unroll
                for (int i = 0; i < 2; i++) {
                    const uint4 v = *reinterpret_cast<const uint4*>(
                        st + ((kk * 8 + wm * 2 + i) << 7) + (lane << 2));
                    ah[i][0] = v.x; ah[i][1] = v.y; ah[i][2] = v.z; ah[i][3] = v.w;
                }
#pragma unroll
                for (int j = 0; j < 8; j++) {
                    const uint2 bh = *reinterpret_cast<const uint2*>(
                        st + BBu + ((kk * 16 + wn * 8 + j) << 6) + (lane << 1));
                    mma16816(acc[0][j], ah[0], bh.x, bh.y);
                    mma16816(acc[1][j], ah[1], bh.x, bh.y);
                }
            }
        }
        if (s + 1 < S) {
            const int rem = S - s - 2;
            if (rem >= NSTG - 2) cp_wait<NSTG - 2>();
            else if (rem == 3) cp_wait<3>();
            else if (rem == 2) cp_wait<2>();
            else if (rem == 1) cp_wait<1>();
            else cp_wait<0>();
            __syncthreads();
        }
        bufC = (bufC + 1 == NSTG) ? 0 : bufC + 1;
        bufI = (bufI + 1 == NSTG) ? 0 : bufI + 1;
    }

    // ---- epilogue ----
    const int tkb = (n0 >> 4) + wn * 4;

    if (mat == 0) {          // theta -> A-layout, MT_out = 64
#pragma unroll
        for (int i = 0; i < 2; i++) {
            const int t_m = (m0 + wm * 32 + i * 16) >> 4;
#pragma unroll
            for (int j2 = 0; j2 < 4; j2++) {
                const int npe = n0 + wn * 64 + j2 * 16 + tig * 2;
                const float2 bE = *reinterpret_cast<const float2*>(bias + npe);
                const float2 bO = *reinterpret_cast<const float2*>(bias + npe + 8);
                const uint32_t H0 = packh1(acc[i][2*j2][0]+bE.x, acc[i][2*j2][1]+bE.y);
                const uint32_t H1 = packh1(acc[i][2*j2][2]+bE.x, acc[i][2*j2][3]+bE.y);
                const uint32_t H2 = packh1(acc[i][2*j2+1][0]+bO.x, acc[i][2*j2+1][1]+bO.y);
                const uint32_t H3 = packh1(acc[i][2*j2+1][2]+bO.x, acc[i][2*j2+1][3]+bO.y);
                const long long off = (long long)((tkb + j2) * 64 + t_m) * 128 + lane * 4;
                *reinterpret_cast<uint4*>(OU + off) = make_uint4(H0, H1, H2, H3);
            }
        }
    } else if (mat == 1) {   // phi -> B-layout, NT8_out = 128
#pragma unroll
        for (int i = 0; i < 2; i++)
#pragma unroll
            for (int h = 0; h < 2; h++) {
                const int t_n = (m0 + wm * 32 + i * 16 + h * 8) >> 3;
#pragma unroll
                for (int j2 = 0; j2 < 4; j2++) {
                    const int npe = n0 + wn * 64 + j2 * 16 + tig * 2;
                    const float2 bE = *reinterpret_cast<const float2*>(bias + npe);
                    const float2 bO = *reinterpret_cast<const float2*>(bias + npe + 8);
                    const uint32_t U0 = packh1(acc[i][2*j2][h*2]+bE.x, acc[i][2*j2][h*2+1]+bE.y);
                    const uint32_t U1 = packh1(acc[i][2*j2+1][h*2]+bO.x, acc[i][2*j2+1][h*2+1]+bO.y);
                    const long long off = (long long)((tkb + j2) * 128 + t_n) * 64 + lane * 2;
                    *reinterpret_cast<uint2*>(OU + off) = make_uint2(U0, U1);
                }
            }
    } else {                 // g -> B-layout, NT8_out = 32, bias over m
#pragma unroll
        for (int i = 0; i < 2; i++)
#pragma unroll
            for (int h = 0; h < 2; h++) {
                const int m = m0 + wm * 32 + i * 16 + grp + h * 8;
                const float bm = bias[m];
                const int t_n = m >> 3;
#pragma unroll
                for (int j2 = 0; j2 < 4; j2++) {
                    const uint32_t U0 = packh1(acc[i][2*j2][h*2] + bm, acc[i][2*j2][h*2+1] + bm);
                    const uint32_t U1 = packh1(acc[i][2*j2+1][h*2] + bm, acc[i][2*j2+1][h*2+1] + bm);
                    const long long off = (long long)((tkb + j2) * 32 + t_n) * 64 + lane * 2;
                    *reinterpret_cast<uint2*>(OU + off) = make_uint2(U0, U1);
                }
            }
    }
}

// ---------------------------------------------------------------------------
// GEMM for KIND 2 (logits + fused softmax), 3 (AV, TRA), 4 (final).
// ---------------------------------------------------------------------------
template <int KIND>
__global__ __launch_bounds__(256, 2)
void tc_gemm(const float* __restrict__ b0, const float* __restrict__ b1,
             const float* __restrict__ i0, const float* __restrict__ i1,
             const float* __restrict__ q0, const float* __restrict__ q1,
             const float* __restrict__ q2, const float* __restrict__ q3,
             const float* __restrict__ q4, const float* __restrict__ q5,
             const float* __restrict__ q6, const float* __restrict__ q7,
             float* outF)
{
    constexpr bool TRA  = (KIND == 3);
    constexpr int  BBu  = 2048;
    constexpr int  STGU = 4096;
    constexpr int  NSTG = 6;
    constexpr int  Kc   = (KIND == 3) ? 1024 : 256;
    constexpr int  MT   = (KIND == 4) ? 32 : 64;
    constexpr int  NT8  = (KIND == 3) ? 32 : 128;

    extern __shared__ uint32_t sm[];
    const uint32_t smb = smem_u32(sm);
    const int tid  = threadIdx.x;
    const int lane = tid & 31;
    const int warp = tid >> 5;
    const int grp  = lane >> 2;
    const int tig  = lane & 3;
    const int wm   = warp & 3;
    const int wn   = warp >> 2;
    const int m0   = blockIdx.y * 128;
    const int n0   = blockIdx.x * 128;
    const int zz   = blockIdx.z;

    const uint32_t *Ah = nullptr, *Bh = nullptr;
    const float* bias = nullptr;
    uint32_t* OU = nullptr;
    float* OF = nullptr;
    int blk = 0, batch = 0;

    if constexpr (KIND == 2) {
        Ah = u_TH + (long long)zz * 131072;
        Bh = u_PH + (long long)zz * 131072;
        OF = g_S + (long long)zz * 1048576;
    } else if constexpr (KIND == 3) {
        Ah = u_P + (long long)zz * 524288;
        Bh = u_G + (long long)zz * 131072;
        OU = u_Y + (long long)zz * 131072;
    } else {
        blk = zz >> 4; batch = zz & 15;
        Ah = u_W + (blk * 4 + 3) * 65536;
        Bh = u_Y + (long long)zz * 131072;
        bias = blk ? b1 : b0;
        OF = outF + (long long)blk * 8388608 + (long long)batch * 524288;
    }

    const int m0t = m0 >> 4, n0t = n0 >> 3;
    const int ml = tid >> 1, half = tid & 1;

    auto issueAB = [&](int s, int buf) {
        const uint32_t base = smb + buf * STGU * 4;
        if (!TRA) {
#pragma unroll
            for (int i = 0; i < 2; i++) {
                const int c = tid + i * 256;
                const int kk = c >> 8, inner = c & 255;
                cp16(base + (c * 4) * 4,
                     Ah + (long long)((s * 2 + kk) * MT + m0t) * 128 + inner * 4);
            }
        }
#pragma unroll
        for (int i = 0; i < 2; i++) {
            const int c = tid + i * 256;
            const int kk = c >> 8, inner = c & 255;
            cp16(base + ((BBu + c * 4)) * 4,
                 Bh + (long long)((s * 2 + kk) * NT8 + n0t) * 64 + inner * 4);
        }
    };

    uint4 pre[2];
    auto ldgA = [&](int s) {
#pragma unroll
        for (int p = 0; p < 2; p++)
            pre[p] = *reinterpret_cast<const uint4*>(
                Ah + (long long)(m0 + ml) * 512 + s * 16 + half * 4 + p * 8);
    };
    auto stsA = [&](int buf) {
        uint32_t* base = sm + buf * STGU;
        const int tml = ml >> 4, l4 = (ml & 7) * 16, rbase = ((ml >> 3) & 1) + half * 2;
#pragma unroll
        for (int p = 0; p < 2; p++) {
            const uint32_t v[4] = {pre[p].x, pre[p].y, pre[p].z, pre[p].w};
#pragma unroll
            for (int jj = 0; jj < 4; jj++)
                base[((p * 8 + tml) << 7) + l4 + jj * 4 + rbase] = v[jj];
        }
    };

    float acc[2][8][4];
#pragma unroll
    for (int i = 0; i < 2; i++)
#pragma unroll
        for (int j = 0; j < 8; j++)
#pragma unroll
            for (int q = 0; q < 4; q++) acc[i][j][q] = 0.f;

    constexpr int S = Kc >> 5;

    if (TRA) {
        ldgA(0);
#pragma unroll
        for (int i = 0; i < NSTG - 1; i++) { issueAB(i, i); CP_COMMIT(); }
        stsA(0); ldgA(1);
    } else {
#pragma unroll
        for (int i = 0; i < NSTG - 1; i++) { issueAB(i, i); CP_COMMIT(); }
    }
    cp_wait<NSTG - 2>();
    __syncthreads();

    int bufC = 0, bufI = NSTG - 1;
    for (int s = 0; s < S; s++) {
        if (s + NSTG - 1 < S) { issueAB(s + NSTG - 1, bufI); CP_COMMIT(); }
        {
            const uint32_t* st = sm + bufC * STGU;
#pragma unroll
            for (int kk = 0; kk < 2; kk++) {
                uint32_t ah[2][4];
#pragma unroll
                for (int i = 0; i < 2; i++) {
                    const uint4 v = *reinterpret_cast<const uint4*>(
                        st + ((kk * 8 + wm * 2 + i) << 7) + (lane << 2));
                    ah[i][0] = v.x; ah[i][1] = v.y; ah[i][2] = v.z; ah[i][3] = v.w;
                }
#pragma unroll
                for (int j = 0; j < 8; j++) {
                    const uint2 bh = *reinterpret_cast<const uint2*>(
                        st + BBu + ((kk * 16 + wn * 8 + j) << 6) + (lane << 1));
                    mma16816(acc[0][j], ah[0], bh.x, bh.y);
                    mma16816(acc[1][j], ah[1], bh.x, bh.y);
                }
            }
        }
        if (s + 1 < S) {
            if (TRA) {
                const int bufN = (bufC + 1 == NSTG) ? 0 : bufC + 1;
                stsA(bufN);
                if (s + 2 < S) ldgA(s + 2);
            }
            const int rem = S - s - 2;
            if (rem >= NSTG - 2) cp_wait<NSTG - 2>();
            else if (rem == 3) cp_wait<3>();
            else if (rem == 2) cp_wait<2>();
            else if (rem == 1) cp_wait<1>();
            else cp_wait<0>();
            __syncthreads();
        }
        bufC = (bufC + 1 == NSTG) ? 0 : bufC + 1;
        bufI = (bufI + 1 == NSTG) ? 0 : bufI + 1;
    }

    // ------------------------------ epilogue ------------------------------
    if constexpr (KIND == 3) {
        const int tkb = (n0 >> 4) + wn * 4;
#pragma unroll
        for (int i = 0; i < 2; i++)
#pragma unroll
            for (int h = 0; h < 2; h++) {
                const int m = m0 + wm * 32 + i * 16 + grp + h * 8;
                const int t_n = m >> 3;
#pragma unroll
                for (int j2 = 0; j2 < 4; j2++) {
                    const uint32_t U0 = packh1(acc[i][2*j2][h*2], acc[i][2*j2][h*2+1]);
                    const uint32_t U1 = packh1(acc[i][2*j2+1][h*2], acc[i][2*j2+1][h*2+1]);
                    const long long off = (long long)((tkb + j2) * 128 + t_n) * 64 + lane * 2;
                    *reinterpret_cast<uint2*>(OU + off) = make_uint2(U0, U1);
                }
            }
    } else {
#pragma unroll
        for (int i = 0; i < 2; i++)
#pragma unroll
            for (int h = 0; h < 2; h++) {
                const int m = m0 + wm * 32 + i * 16 + grp + h * 8;
                float bm = 0.f, sc = 0.f, sh = 0.f;
                const float* inp = nullptr;
                if constexpr (KIND == 4) {
                    bm = bias[m];
                    const float* bg  = blk ? q4 : q0;
                    const float* bb  = blk ? q5 : q1;
                    const float* bmn = blk ? q6 : q2;
                    const float* bv  = blk ? q7 : q3;
                    sc = bg[m] * rsqrtf(bv[m] + 1e-5f);
                    sh = bb[m] - bmn[m] * sc;
                    inp = (blk ? i1 : i0) + (long long)batch * 524288 + (long long)m * 1024;
                }
#pragma unroll
                for (int j = 0; j < 8; j++) {
                    const int np = n0 + wn * 64 + j * 8 + tig * 2;
                    const float v0 = acc[i][j][h * 2];
                    const float v1 = acc[i][j][h * 2 + 1];
                    if constexpr (KIND == 2) {
                        *reinterpret_cast<float2*>(OF + (long long)m * 1024 + np) =
                            make_float2(v0, v1);
                    } else {
                        const float2 x = *reinterpret_cast<const float2*>(inp + np);
                        const float r0v = fmaxf(fmaf(x.x, sc, sh), 0.f);
                        const float r1v = fmaxf(fmaf(x.y, sc, sh), 0.f);
                        *reinterpret_cast<float2*>(OF + (long long)m * 1024 + np) =
                            make_float2(v0 + bm + r0v, v1 + bm + r1v);
                    }
                }
            }
    }

    // ---- KIND 2: fused softmax (last CTA of the 8 col-CTAs finishes rows) ----
    if constexpr (KIND == 2) {
        __shared__ int s_last;
        __threadfence();
        __syncthreads();
        if (tid == 0) {
            const int cid = zz * 8 + (m0 >> 7);
            const int old = atomicAdd(&g_cnt[cid], 1);
            s_last = (old == 7);
            if (old == 7) g_cnt[cid] = 0;   // reset for next graph replay
        }
        __syncthreads();
        if (!s_last) return;
        __threadfence();   // acquire: see all 8 CTAs' S writes

        // 8 warps x 16 rows each; warp-level softmax over 1024 cols.
        const float* Sz = g_S + (long long)zz * 1048576;
        uint32_t* Pz = u_P + (long long)zz * 524288;
        for (int r = 0; r < 16; r++) {
            const int row = m0 + warp * 16 + r;
            const float4* src = reinterpret_cast<const float4*>(Sz + (long long)row * 1024);
            float4 v[8];
            float mx = -1e30f;
#pragma unroll
            for (int i = 0; i < 8; i++) {
                v[i] = src[lane + i * 32];
                mx = fmaxf(mx, fmaxf(fmaxf(v[i].x, v[i].y), fmaxf(v[i].z, v[i].w)));
            }
#pragma unroll
            for (int o = 16; o > 0; o >>= 1)
                mx = fmaxf(mx, __shfl_xor_sync(0xFFFFFFFFu, mx, o));
            float sum = 0.f;
#pragma unroll
            for (int i = 0; i < 8; i++) {
                v[i].x = expf(v[i].x - mx); v[i].y = expf(v[i].y - mx);
                v[i].z = expf(v[i].z - mx); v[i].w = expf(v[i].w - mx);
                sum += (v[i].x + v[i].y) + (v[i].z + v[i].w);
            }
#pragma unroll
            for (int o = 16; o > 0; o >>= 1)
                sum += __shfl_xor_sync(0xFFFFFFFFu, sum, o);
            const float inv = 1.0f / sum;
            uint32_t* dst = Pz + (long long)row * 512;
#pragma unroll
            for (int i = 0; i < 8; i++) {
                uint2 o2;
                o2.x = packh1(v[i].x * inv, v[i].y * inv);
                o2.y = packh1(v[i].z * inv, v[i].w * inv);
                *reinterpret_cast<uint2*>(dst + lane * 2 + i * 64) = o2;
            }
        }
    }
}

// ---------------------------------------------------------------------------
// Launcher. 5 launches.
// ---------------------------------------------------------------------------
extern "C" void kernel_launch(void* const* d_in, const int* in_sizes, int n_in,
                              void* d_out, int out_size)
{
    cudaFuncSetAttribute(gemm01,     cudaFuncAttributeMaxDynamicSharedMemorySize, 98304);
    cudaFuncSetAttribute(tc_gemm<2>, cudaFuncAttributeMaxDynamicSharedMemorySize, 98304);
    cudaFuncSetAttribute(tc_gemm<3>, cudaFuncAttributeMaxDynamicSharedMemorySize, 98304);
    cudaFuncSetAttribute(tc_gemm<4>, cudaFuncAttributeMaxDynamicSharedMemorySize, 98304);

    const float* F = nullptr;

    prep_all<<<4608, 256>>>(
        (const float*)d_in[0], (const float*)d_in[1],
        (const float*)d_in[2],  (const float*)d_in[3],
        (const float*)d_in[4],  (const float*)d_in[5],
        (const float*)d_in[14], (const float*)d_in[15],
        (const float*)d_in[16], (const float*)d_in[17],
        (const float*)d_in[6],  (const float*)d_in[8],  (const float*)d_in[10], (const float*)d_in[12],
        (const float*)d_in[18], (const float*)d_in[20], (const float*)d_in[22], (const float*)d_in[24]);

    // theta + phi (zz 0..63) + g (zz 64..95)
    gemm01<<<dim3(16, 1, 96), 256, 98304>>>(
        (const float*)d_in[7],  (const float*)d_in[9],
        (const float*)d_in[19], (const float*)d_in[21],
        (const float*)d_in[11], (const float*)d_in[23]);

    // logits + fused softmax (z = 32)
    tc_gemm<2><<<dim3(8, 8, 32), 256, 98304>>>(
        F, F, F, F, F, F, F, F, F, F, F, F, nullptr);

    // AV (z = 32)
    tc_gemm<3><<<dim3(2, 8, 32), 256, 98304>>>(
        F, F, F, F, F, F, F, F, F, F, F, F, nullptr);

    // final (z = 32)
    tc_gemm<4><<<dim3(8, 4, 32), 256, 98304>>>(
        (const float*)d_in[13], (const float*)d_in[25],
        (const float*)d_in[0],  (const float*)d_in[1],
        (const float*)d_in[2],  (const float*)d_in[3],
        (const float*)d_in[4],  (const float*)d_in[5],
        (const float*)d_in[14], (const float*)d_in[15],
        (const float*)d_in[16], (const float*)d_in[17],
        (float*)d_out);
}

// round 13
// speedup vs baseline: 1.1470x; 1.1470x over previous
#include <cuda_runtime.h>
#include <cuda_fp16.h>
#include <cstdint>

#define BATCH 16
#define CCH   512
#define CIN   256
#define NUM   1024

// ---------------------------------------------------------------------------
// Fragment-major global buffers (u32 = fp16 k-pair), hi-precision only.
// A-layout: [k16][m16][128]  lane l owns u32 l*4+{0..3} = {a0,a1,a2,a3}
// B-layout: [k16][n8][64]    lane l owns u32 l*2+{0,1}  = {b0,b1}
// ---------------------------------------------------------------------------
__device__ uint32_t u_XA0[4194304];  // bn1(rgb)  A-layout [16][32][64][128]
__device__ uint32_t u_XA1[4194304];  // bn1(flow)
__device__ uint32_t u_XA2[4194304];  // bn2(flow)
__device__ uint32_t u_XA3[4194304];  // bn2(rgb)
__device__ uint32_t u_XB0[4194304];  // bn1(rgb)  B-layout
__device__ uint32_t u_XB1[4194304];  // bn2(flow) B-layout
__device__ uint32_t u_TH[4194304];   // theta A-layout [32][16][64][128]
__device__ uint32_t u_PH[4194304];   // phi   B-layout [32][16][128][64]
__device__ uint32_t u_G [4194304];   // g     B-layout [32][64][32][64]
__device__ uint32_t u_Y [4194304];   // y     B-layout [32][16][128][64]
__device__ uint32_t u_W [524288];    // 8 mats: th/ph B-layout, g/w A-layout
__device__ uint32_t u_P [16777216];  // probs A-layout [32][64 ktile][64 mtile][128]
__device__ float    g_S [33554432];  // logits fp32 [32][1024][1024]

__device__ __forceinline__ uint32_t* xbufA(int s) {
    switch (s) { case 0: return u_XA0; case 1: return u_XA1;
                 case 2: return u_XA2; default: return u_XA3; }
}

// ---------------------------------------------------------------------------
// Helpers
// ---------------------------------------------------------------------------
__device__ __forceinline__ uint32_t smem_u32(const void* p) {
    uint32_t a;
    asm("{ .reg .u64 t; cvta.to.shared.u64 t, %1; cvt.u32.u64 %0, t; }" : "=r"(a) : "l"(p));
    return a;
}
__device__ __forceinline__ void cp16(uint32_t dst, const void* src) {
    asm volatile("cp.async.cg.shared.global [%0], [%1], 16;" :: "r"(dst), "l"(src));
}
#define CP_COMMIT() asm volatile("cp.async.commit_group;")
template <int N>
__device__ __forceinline__ void cp_wait() {
    asm volatile("cp.async.wait_group %0;" :: "n"(N));
}

__device__ __forceinline__ uint32_t packh1(float x, float y) {
    __half2 H = __halves2half2(__float2half_rn(x), __float2half_rn(y));
    return *reinterpret_cast<uint32_t*>(&H);
}

__device__ __forceinline__ void mma16816(float c[4], const uint32_t a[4],
                                         uint32_t b0, uint32_t b1) {
    asm volatile(
        "mma.sync.aligned.m16n8k16.row.col.f32.f16.f16.f32 "
        "{%0,%1,%2,%3}, {%4,%5,%6,%7}, {%8,%9}, {%0,%1,%2,%3};"
        : "+f"(c[0]), "+f"(c[1]), "+f"(c[2]), "+f"(c[3])
        : "r"(a[0]), "r"(a[1]), "r"(a[2]), "r"(a[3]), "r"(b0), "r"(b1));
}

// ---------------------------------------------------------------------------
// Fused prep: BN+ReLU fragment tiles (blocks 0..4095) + weight prep (4096..4607).
// ---------------------------------------------------------------------------
__global__ void prep_all(const float* __restrict__ rgb, const float* __restrict__ flow,
                         const float* __restrict__ g1, const float* __restrict__ b1,
                         const float* __restrict__ m1, const float* __restrict__ v1,
                         const float* __restrict__ g2, const float* __restrict__ b2,
                         const float* __restrict__ m2, const float* __restrict__ v2,
                         const float* w0, const float* w1, const float* w2, const float* w3,
                         const float* w4, const float* w5, const float* w6, const float* w7)
{
    const int bid = blockIdx.x;
    const int warp = threadIdx.x >> 5, lane = threadIdx.x & 31;
    const int grp = lane >> 2, tig = lane & 3;

    if (bid < 4096) {
        const int z = bid >> 8;
        const int id = (bid & 255) * 8 + warp;
        const int t_k = id & 31, t_n = id >> 5;
        const int n0 = t_n * 16;

        int c[4];
        c[0] = t_k * 16 + 2 * tig; c[1] = c[0] + 1; c[2] = c[0] + 8; c[3] = c[2] + 1;

        float s1[4], h1[4], s2[4], h2[4];
#pragma unroll
        for (int e = 0; e < 4; e++) {
            s1[e] = g1[c[e]] * rsqrtf(v1[c[e]] + 1e-5f);
            h1[e] = b1[c[e]] - m1[c[e]] * s1[e];
            s2[e] = g2[c[e]] * rsqrtf(v2[c[e]] + 1e-5f);
            h2[e] = b2[c[e]] - m2[c[e]] * s2[e];
        }

        float R[2][4], Fv[2][4];
#pragma unroll
        for (int h = 0; h < 2; h++)
#pragma unroll
            for (int e = 0; e < 4; e++) {
                const long long idx = (long long)(z * CCH + c[e]) * NUM + n0 + grp + h * 8;
                R[h][e] = rgb[idx];
                Fv[h][e] = flow[idx];
            }

        auto bnr = [](float x, float s, float h) { return fmaxf(fmaf(x, s, h), 0.f); };
        const long long aoff = (long long)z * 262144 + (t_k * 64 + t_n) * 128 + lane * 4;
        const long long boff = (long long)z * 262144 + (long long)(t_k * 128 + t_n * 2) * 64 + lane * 2;

        float V[2][4];
        auto doStream = [&](const float (*X)[4], const float* sc, const float* sh,
                            uint32_t* bufA, uint32_t* bufB) {
#pragma unroll
            for (int h = 0; h < 2; h++)
#pragma unroll
                for (int e = 0; e < 4; e++) V[h][e] = bnr(X[h][e], sc[e], sh[e]);
            const uint32_t H0 = packh1(V[0][0], V[0][1]);
            const uint32_t H1 = packh1(V[1][0], V[1][1]);
            const uint32_t H2 = packh1(V[0][2], V[0][3]);
            const uint32_t H3 = packh1(V[1][2], V[1][3]);
            *reinterpret_cast<uint4*>(bufA + aoff) = make_uint4(H0, H1, H2, H3);
            if (bufB) {
                *reinterpret_cast<uint2*>(bufB + boff)      = make_uint2(H0, H2);
                *reinterpret_cast<uint2*>(bufB + boff + 64) = make_uint2(H1, H3);
            }
        };
        doStream(R,  s1, h1, u_XA0, u_XB0);
        doStream(Fv, s1, h1, u_XA1, nullptr);
        doStream(Fv, s2, h2, u_XA2, u_XB1);
        doStream(R,  s2, h2, u_XA3, nullptr);
    } else {
        const int w = bid - 4096;
        const int mat = w >> 6;
        const bool isW = ((mat & 3) == 3);
        const int din  = isW ? 256 : 512;
        const int dout = isW ? 512 : 256;
        const bool Asw = ((mat & 3) >= 2);
        const int id = (w & 63) * 8 + warp;
        const int kT = din >> 4;
        const int t_k = id % kT, t_m = id / kT;

        const float* src;
        switch (mat) {
            case 0: src = w0; break; case 1: src = w1; break;
            case 2: src = w2; break; case 3: src = w3; break;
            case 4: src = w4; break; case 5: src = w5; break;
            case 6: src = w6; break; default: src = w7; break;
        }

        uint32_t u[2][2];
#pragma unroll
        for (int h = 0; h < 2; h++)
#pragma unroll
            for (int q = 0; q < 2; q++) {
                const int row = t_m * 16 + grp + h * 8;
                const int col = t_k * 16 + 2 * tig + 8 * q;
                const float2 f = *reinterpret_cast<const float2*>(src + (long long)row * din + col);
                u[h][q] = packh1(f.x, f.y);
            }
        uint32_t* base = u_W + mat * 65536;
        if (Asw) {
            *reinterpret_cast<uint4*>(base + (t_k * (dout >> 4) + t_m) * 128 + lane * 4) =
                make_uint4(u[0][0], u[1][0], u[0][1], u[1][1]);
        } else {
#pragma unroll
            for (int h = 0; h < 2; h++)
                *reinterpret_cast<uint2*>(base + (t_k * (dout >> 3) + t_m * 2 + h) * 64 + lane * 2) =
                    make_uint2(u[h][0], u[h][1]);
        }
    }
}

// ---------------------------------------------------------------------------
// Merged theta/phi/g GEMM. grid (16, 1, 96): zz<64 -> thph, zz>=64 -> g.
// ---------------------------------------------------------------------------
__global__ __launch_bounds__(256, 2)
void gemm01(const float* __restrict__ tb1, const float* __restrict__ pb1,
            const float* __restrict__ tb2, const float* __restrict__ pb2,
            const float* __restrict__ gb1, const float* __restrict__ gb2)
{
    constexpr int BBu = 2048, STGU = 4096, NSTG = 6, S = 16;  // K = 512

    extern __shared__ uint32_t sm[];
    const uint32_t smb = smem_u32(sm);
    const int tid  = threadIdx.x;
    const int lane = tid & 31;
    const int warp = tid >> 5;
    const int grp  = lane >> 2;
    const int tig  = lane & 3;
    const int wm   = warp & 3;
    const int wn   = warp >> 2;
    const int tx   = blockIdx.x;
    const int zz   = blockIdx.z;

    const uint32_t *Ah, *Bh;
    const float* bias;
    uint32_t* OU;
    int MTr, NT8r, m0, n0, mat;

    if (zz < 64) {
        const int batch = zz & 15, sel = zz >> 4, blk = sel >> 1;
        mat = sel & 1;
        Ah = xbufA(sel) + (long long)batch * 262144;
        Bh = u_W + (blk * 4 + mat) * 65536;
        bias = (sel == 0) ? tb1 : (sel == 1) ? pb1 : (sel == 2) ? tb2 : pb2;
        OU = (mat ? u_PH : u_TH) + (long long)(blk * 16 + batch) * 131072;
        MTr = 64; NT8r = 32;
        m0 = (tx >> 1) * 128; n0 = (tx & 1) * 128;
    } else {
        const int z2 = zz - 64, blk = z2 >> 4, batch = z2 & 15;
        mat = 2;
        Ah = u_W + (blk * 4 + 2) * 65536;
        Bh = (blk ? u_XB1 : u_XB0) + (long long)batch * 262144;
        bias = blk ? gb2 : gb1;
        OU = u_G + (long long)z2 * 131072;
        MTr = 16; NT8r = 128;
        m0 = (tx & 1) * 128; n0 = (tx >> 1) * 128;
    }

    const int m0t = m0 >> 4, n0t = n0 >> 3;

    auto issueAB = [&](int s, int buf) {
        const uint32_t base = smb + buf * STGU * 4;
#pragma unroll
        for (int i = 0; i < 2; i++) {
            const int c = tid + i * 256;
            const int kk = c >> 8, inner = c & 255;
            cp16(base + (c * 4) * 4,
                 Ah + (long long)((s * 2 + kk) * MTr + m0t) * 128 + inner * 4);
        }
#pragma unroll
        for (int i = 0; i < 2; i++) {
            const int c = tid + i * 256;
            const int kk = c >> 8, inner = c & 255;
            cp16(base + ((BBu + c * 4)) * 4,
                 Bh + (long long)((s * 2 + kk) * NT8r + n0t) * 64 + inner * 4);
        }
    };

    float acc[2][8][4];
#pragma unroll
    for (int i = 0; i < 2; i++)
#pragma unroll
        for (int j = 0; j < 8; j++)
#pragma unroll
            for (int q = 0; q < 4; q++) acc[i][j][q] = 0.f;

#pragma unroll
    for (int i = 0; i < NSTG - 1; i++) { issueAB(i, i); CP_COMMIT(); }
    cp_wait<NSTG - 2>();
    __syncthreads();

    int bufC = 0, bufI = NSTG - 1;
    for (int s = 0; s < S; s++) {
        if (s + NSTG - 1 < S) { issueAB(s + NSTG - 1, bufI); CP_COMMIT(); }
        {
            const uint32_t* st = sm + bufC * STGU;
#pragma unroll
            for (int kk = 0; kk < 2; kk++) {
                uint32_t ah[2][4];
#pragma unroll
                for (int i = 0; i < 2; i++) {
                    const uint4 v = *reinterpret_cast<const uint4*>(
                        st + ((kk * 8 + wm * 2 + i) << 7) + (lane << 2));
                    ah[i][0] = v.x; ah[i][1] = v.y; ah[i][2] = v.z; ah[i][3] = v.w;
                }
#pragma unroll
                for (int j = 0; j < 8; j++) {
                    const uint2 bh = *reinterpret_cast<const uint2*>(
                        st + BBu + ((kk * 16 + wn * 8 + j) << 6) + (lane << 1));
                    mma16816(acc[0][j], ah[0], bh.x, bh.y);
                    mma16816(acc[1][j], ah[1], bh.x, bh.y);
                }
            }
        }
        if (s + 1 < S) {
            const int rem = S - s - 2;
            if (rem >= NSTG - 2) cp_wait<NSTG - 2>();
            else if (rem == 3) cp_wait<3>();
            else if (rem == 2) cp_wait<2>();
            else if (rem == 1) cp_wait<1>();
            else cp_wait<0>();
            __syncthreads();
        }
        bufC = (bufC + 1 == NSTG) ? 0 : bufC + 1;
        bufI = (bufI + 1 == NSTG) ? 0 : bufI + 1;
    }

    // ---- epilogue ----
    const int tkb = (n0 >> 4) + wn * 4;

    if (mat == 0) {          // theta -> A-layout, MT_out = 64
#pragma unroll
        for (int i = 0; i < 2; i++) {
            const int t_m = (m0 + wm * 32 + i * 16) >> 4;
#pragma unroll
            for (int j2 = 0; j2 < 4; j2++) {
                const int npe = n0 + wn * 64 + j2 * 16 + tig * 2;
                const float2 bE = *reinterpret_cast<const float2*>(bias + npe);
                const float2 bO = *reinterpret_cast<const float2*>(bias + npe + 8);
                const uint32_t H0 = packh1(acc[i][2*j2][0]+bE.x, acc[i][2*j2][1]+bE.y);
                const uint32_t H1 = packh1(acc[i][2*j2][2]+bE.x, acc[i][2*j2][3]+bE.y);
                const uint32_t H2 = packh1(acc[i][2*j2+1][0]+bO.x, acc[i][2*j2+1][1]+bO.y);
                const uint32_t H3 = packh1(acc[i][2*j2+1][2]+bO.x, acc[i][2*j2+1][3]+bO.y);
                const long long off = (long long)((tkb + j2) * 64 + t_m) * 128 + lane * 4;
                *reinterpret_cast<uint4*>(OU + off) = make_uint4(H0, H1, H2, H3);
            }
        }
    } else if (mat == 1) {   // phi -> B-layout, NT8_out = 128
#pragma unroll
        for (int i = 0; i < 2; i++)
#pragma unroll
            for (int h = 0; h < 2; h++) {
                const int t_n = (m0 + wm * 32 + i * 16 + h * 8) >> 3;
#pragma unroll
                for (int j2 = 0; j2 < 4; j2++) {
                    const int npe = n0 + wn * 64 + j2 * 16 + tig * 2;
                    const float2 bE = *reinterpret_cast<const float2*>(bias + npe);
                    const float2 bO = *reinterpret_cast<const float2*>(bias + npe + 8);
                    const uint32_t U0 = packh1(acc[i][2*j2][h*2]+bE.x, acc[i][2*j2][h*2+1]+bE.y);
                    const uint32_t U1 = packh1(acc[i][2*j2+1][h*2]+bO.x, acc[i][2*j2+1][h*2+1]+bO.y);
                    const long long off = (long long)((tkb + j2) * 128 + t_n) * 64 + lane * 2;
                    *reinterpret_cast<uint2*>(OU + off) = make_uint2(U0, U1);
                }
            }
    } else {                 // g -> B-layout, NT8_out = 32, bias over m
#pragma unroll
        for (int i = 0; i < 2; i++)
#pragma unroll
            for (int h = 0; h < 2; h++) {
                const int m = m0 + wm * 32 + i * 16 + grp + h * 8;
                const float bm = bias[m];
                const int t_n = m >> 3;
#pragma unroll
                for (int j2 = 0; j2 < 4; j2++) {
                    const uint32_t U0 = packh1(acc[i][2*j2][h*2] + bm, acc[i][2*j2][h*2+1] + bm);
                    const uint32_t U1 = packh1(acc[i][2*j2+1][h*2] + bm, acc[i][2*j2+1][h*2+1] + bm);
                    const long long off = (long long)((tkb + j2) * 32 + t_n) * 64 + lane * 2;
                    *reinterpret_cast<uint2*>(OU + off) = make_uint2(U0, U1);
                }
            }
    }
}

// ---------------------------------------------------------------------------
// GEMM for KIND 2 (logits), 3 (AV, A-layout probs), 4 (final).
// All standard cp.async path (no TRA anymore).
// ---------------------------------------------------------------------------
template <int KIND>
__global__ __launch_bounds__(256, 2)
void tc_gemm(const float* __restrict__ b0, const float* __restrict__ b1,
             const float* __restrict__ i0, const float* __restrict__ i1,
             const float* __restrict__ q0, const float* __restrict__ q1,
             const float* __restrict__ q2, const float* __restrict__ q3,
             const float* __restrict__ q4, const float* __restrict__ q5,
             const float* __restrict__ q6, const float* __restrict__ q7,
             float* outF)
{
    constexpr int  BBu  = 2048;
    constexpr int  STGU = 4096;
    constexpr int  NSTG = 6;
    constexpr int  Kc   = (KIND == 3) ? 1024 : 256;
    constexpr int  MT   = (KIND == 4) ? 32 : 64;
    constexpr int  NT8  = (KIND == 3) ? 32 : 128;

    extern __shared__ uint32_t sm[];
    const uint32_t smb = smem_u32(sm);
    const int tid  = threadIdx.x;
    const int lane = tid & 31;
    const int warp = tid >> 5;
    const int grp  = lane >> 2;
    const int tig  = lane & 3;
    const int wm   = warp & 3;
    const int wn   = warp >> 2;
    const int m0   = blockIdx.y * 128;
    const int n0   = blockIdx.x * 128;
    const int zz   = blockIdx.z;

    const uint32_t *Ah = nullptr, *Bh = nullptr;
    const float* bias = nullptr;
    uint32_t* OU = nullptr;
    float* OF = nullptr;
    int blk = 0, batch = 0;

    if constexpr (KIND == 2) {
        Ah = u_TH + (long long)zz * 131072;
        Bh = u_PH + (long long)zz * 131072;
        OF = g_S + (long long)zz * 1048576;
    } else if constexpr (KIND == 3) {
        Ah = u_P + (long long)zz * 524288;    // A-layout probs [64][64][128]
        Bh = u_G + (long long)zz * 131072;
        OU = u_Y + (long long)zz * 131072;
    } else {
        blk = zz >> 4; batch = zz & 15;
        Ah = u_W + (blk * 4 + 3) * 65536;
        Bh = u_Y + (long long)zz * 131072;
        bias = blk ? b1 : b0;
        OF = outF + (long long)blk * 8388608 + (long long)batch * 524288;
    }

    const int m0t = m0 >> 4, n0t = n0 >> 3;

    auto issueAB = [&](int s, int buf) {
        const uint32_t base = smb + buf * STGU * 4;
#pragma unroll
        for (int i = 0; i < 2; i++) {
            const int c = tid + i * 256;
            const int kk = c >> 8, inner = c & 255;
            cp16(base + (c * 4) * 4,
                 Ah + (long long)((s * 2 + kk) * MT + m0t) * 128 + inner * 4);
        }
#pragma unroll
        for (int i = 0; i < 2; i++) {
            const int c = tid + i * 256;
            const int kk = c >> 8, inner = c & 255;
            cp16(base + ((BBu + c * 4)) * 4,
                 Bh + (long long)((s * 2 + kk) * NT8 + n0t) * 64 + inner * 4);
        }
    };

    float acc[2][8][4];
#pragma unroll
    for (int i = 0; i < 2; i++)
#pragma unroll
        for (int j = 0; j < 8; j++)
#pragma unroll
            for (int q = 0; q < 4; q++) acc[i][j][q] = 0.f;

    constexpr int S = Kc >> 5;

#pragma unroll
    for (int i = 0; i < NSTG - 1; i++) { issueAB(i, i); CP_COMMIT(); }
    cp_wait<NSTG - 2>();
    __syncthreads();

    int bufC = 0, bufI = NSTG - 1;
    for (int s = 0; s < S; s++) {
        if (s + NSTG - 1 < S) { issueAB(s + NSTG - 1, bufI); CP_COMMIT(); }
        {
            const uint32_t* st = sm + bufC * STGU;
#pragma unroll
            for (int kk = 0; kk < 2; kk++) {
                uint32_t ah[2][4];
#pragma unroll
                for (int i = 0; i < 2; i++) {
                    const uint4 v = *reinterpret_cast<const uint4*>(
                        st + ((kk * 8 + wm * 2 + i) << 7) + (lane << 2));
                    ah[i][0] = v.x; ah[i][1] = v.y; ah[i][2] = v.z; ah[i][3] = v.w;
                }
#pragma unroll
                for (int j = 0; j < 8; j++) {
                    const uint2 bh = *reinterpret_cast<const uint2*>(
                        st + BBu + ((kk * 16 + wn * 8 + j) << 6) + (lane << 1));
                    mma16816(acc[0][j], ah[0], bh.x, bh.y);
                    mma16816(acc[1][j], ah[1], bh.x, bh.y);
                }
            }
        }
        if (s + 1 < S) {
            const int rem = S - s - 2;
            if (rem >= NSTG - 2) cp_wait<NSTG - 2>();
            else if (rem == 3) cp_wait<3>();
            else if (rem == 2) cp_wait<2>();
            else if (rem == 1) cp_wait<1>();
            else cp_wait<0>();
            __syncthreads();
        }
        bufC = (bufC + 1 == NSTG) ? 0 : bufC + 1;
        bufI = (bufI + 1 == NSTG) ? 0 : bufI + 1;
    }

    // ------------------------------ epilogue ------------------------------
    if constexpr (KIND == 3) {
        const int tkb = (n0 >> 4) + wn * 4;
#pragma unroll
        for (int i = 0; i < 2; i++)
#pragma unroll
            for (int h = 0; h < 2; h++) {
                const int m = m0 + wm * 32 + i * 16 + grp + h * 8;
                const int t_n = m >> 3;
#pragma unroll
                for (int j2 = 0; j2 < 4; j2++) {
                    const uint32_t U0 = packh1(acc[i][2*j2][h*2], acc[i][2*j2][h*2+1]);
                    const uint32_t U1 = packh1(acc[i][2*j2+1][h*2], acc[i][2*j2+1][h*2+1]);
                    const long long off = (long long)((tkb + j2) * 128 + t_n) * 64 + lane * 2;
                    *reinterpret_cast<uint2*>(OU + off) = make_uint2(U0, U1);
                }
            }
    } else {
#pragma unroll
        for (int i = 0; i < 2; i++)
#pragma unroll
            for (int h = 0; h < 2; h++) {
                const int m = m0 + wm * 32 + i * 16 + grp + h * 8;
                float bm = 0.f, sc = 0.f, sh = 0.f;
                const float* inp = nullptr;
                if constexpr (KIND == 4) {
                    bm = bias[m];
                    const float* bg  = blk ? q4 : q0;
                    const float* bb  = blk ? q5 : q1;
                    const float* bmn = blk ? q6 : q2;
                    const float* bv  = blk ? q7 : q3;
                    sc = bg[m] * rsqrtf(bv[m] + 1e-5f);
                    sh = bb[m] - bmn[m] * sc;
                    inp = (blk ? i1 : i0) + (long long)batch * 524288 + (long long)m * 1024;
                }
#pragma unroll
                for (int j = 0; j < 8; j++) {
                    const int np = n0 + wn * 64 + j * 8 + tig * 2;
                    const float v0 = acc[i][j][h * 2];
                    const float v1 = acc[i][j][h * 2 + 1];
                    if constexpr (KIND == 2) {
                        *reinterpret_cast<float2*>(OF + (long long)m * 1024 + np) =
                            make_float2(v0, v1);
                    } else {
                        const float2 x = *reinterpret_cast<const float2*>(inp + np);
                        const float r0v = fmaxf(fmaf(x.x, sc, sh), 0.f);
                        const float r1v = fmaxf(fmaf(x.y, sc, sh), 0.f);
                        *reinterpret_cast<float2*>(OF + (long long)m * 1024 + np) =
                            make_float2(v0 + bm + r0v, v1 + bm + r1v);
                    }
                }
            }
    }
}

// ---------------------------------------------------------------------------
// Softmax: block per 16-row tile, emits u_P directly in A-fragment layout.
// grid (64 row-tiles, 32 z), 256 threads. smem rows padded to 516 u32 so the
// fragment gather (bank = (4m+kp)&31) is conflict-free.
// ---------------------------------------------------------------------------
__global__ void softmax_pack()
{
    __shared__ uint32_t sp[16][516];
    const int z = blockIdx.y, t_m = blockIdx.x;
    const int warp = threadIdx.x >> 5, lane = threadIdx.x & 31;
    const float* Sz = g_S + (long long)z * 1048576;

#pragma unroll 1
    for (int rr = 0; rr < 2; rr++) {
        const int mloc = warp * 2 + rr;
        const float4* src = reinterpret_cast<const float4*>(
            Sz + (long long)(t_m * 16 + mloc) * 1024);
        float4 v[8];
        float mx = -1e30f;
#pragma unroll
        for (int i = 0; i < 8; i++) {
            v[i] = src[lane + i * 32];
            mx = fmaxf(mx, fmaxf(fmaxf(v[i].x, v[i].y), fmaxf(v[i].z, v[i].w)));
        }
#pragma unroll
        for (int o = 16; o > 0; o >>= 1)
            mx = fmaxf(mx, __shfl_xor_sync(0xFFFFFFFFu, mx, o));
        float sum = 0.f;
#pragma unroll
        for (int i = 0; i < 8; i++) {
            v[i].x = expf(v[i].x - mx); v[i].y = expf(v[i].y - mx);
            v[i].z = expf(v[i].z - mx); v[i].w = expf(v[i].w - mx);
            sum += (v[i].x + v[i].y) + (v[i].z + v[i].w);
        }
#pragma unroll
        for (int o = 16; o > 0; o >>= 1)
            sum += __shfl_xor_sync(0xFFFFFFFFu, sum, o);
        const float inv = 1.0f / sum;
#pragma unroll
        for (int i = 0; i < 8; i++) {
            uint2 o2;
            o2.x = packh1(v[i].x * inv, v[i].y * inv);
            o2.y = packh1(v[i].z * inv, v[i].w * inv);
            *reinterpret_cast<uint2*>(&sp[mloc][2 * (lane + i * 32)]) = o2;
        }
    }
    __syncthreads();

    // A-layout store: 64 k16 tiles x 128 u32, this block's m16 tile = t_m.
    uint32_t* dst = u_P + (long long)z * 524288 + t_m * 128;
    const int g8 = lane >> 2, t4 = lane & 3;
#pragma unroll
    for (int tt = 0; tt < 8; tt++) {
        const int t_k = warp * 8 + tt;
        const int kb = t_k * 8 + t4;
        const uint4 o = make_uint4(sp[g8][kb], sp[g8 + 8][kb],
                                   sp[g8][kb + 4], sp[g8 + 8][kb + 4]);
        *reinterpret_cast<uint4*>(dst + (long long)t_k * 8192 + lane * 4) = o;
    }
}

// ---------------------------------------------------------------------------
// Launcher. 6 launches.
// ---------------------------------------------------------------------------
extern "C" void kernel_launch(void* const* d_in, const int* in_sizes, int n_in,
                              void* d_out, int out_size)
{
    cudaFuncSetAttribute(gemm01,     cudaFuncAttributeMaxDynamicSharedMemorySize, 98304);
    cudaFuncSetAttribute(tc_gemm<2>, cudaFuncAttributeMaxDynamicSharedMemorySize, 98304);
    cudaFuncSetAttribute(tc_gemm<3>, cudaFuncAttributeMaxDynamicSharedMemorySize, 98304);
    cudaFuncSetAttribute(tc_gemm<4>, cudaFuncAttributeMaxDynamicSharedMemorySize, 98304);

    const float* F = nullptr;

    prep_all<<<4608, 256>>>(
        (const float*)d_in[0], (const float*)d_in[1],
        (const float*)d_in[2],  (const float*)d_in[3],
        (const float*)d_in[4],  (const float*)d_in[5],
        (const float*)d_in[14], (const float*)d_in[15],
        (const float*)d_in[16], (const float*)d_in[17],
        (const float*)d_in[6],  (const float*)d_in[8],  (const float*)d_in[10], (const float*)d_in[12],
        (const float*)d_in[18], (const float*)d_in[20], (const float*)d_in[22], (const float*)d_in[24]);

    // theta + phi (zz 0..63) + g (zz 64..95)
    gemm01<<<dim3(16, 1, 96), 256, 98304>>>(
        (const float*)d_in[7],  (const float*)d_in[9],
        (const float*)d_in[19], (const float*)d_in[21],
        (const float*)d_in[11], (const float*)d_in[23]);

    // logits (z = 32)
    tc_gemm<2><<<dim3(8, 8, 32), 256, 98304>>>(
        F, F, F, F, F, F, F, F, F, F, F, F, nullptr);

    // softmax -> A-layout probs
    softmax_pack<<<dim3(64, 32), 256>>>();

    // AV (z = 32)
    tc_gemm<3><<<dim3(2, 8, 32), 256, 98304>>>(
        F, F, F, F, F, F, F, F, F, F, F, F, nullptr);

    // final (z = 32)
    tc_gemm<4><<<dim3(8, 4, 32), 256, 98304>>>(
        (const float*)d_in[13], (const float*)d_in[25],
        (const float*)d_in[0],  (const float*)d_in[1],
        (const float*)d_in[2],  (const float*)d_in[3],
        (const float*)d_in[4],  (const float*)d_in[5],
        (const float*)d_in[14], (const float*)d_in[15],
        (const float*)d_in[16], (const float*)d_in[17],
        (float*)d_out);
}